// round 4
// baseline (speedup 1.0000x reference)
#include <cuda_runtime.h>
#include <cuda_bf16.h>
#include <math.h>

// ---------------- problem constants ----------------
#define BATCH 4
#define DIM 96
#define DI 192           // D_INNER
#define NST 16           // D_STATE
#define DTR 6            // DT_RANK
#define KDIR 4
#define HID 384
#define HH 64
#define WW 64
#define LL 4096          // H*W
#define MTOK (BATCH*LL)  // 16384

// ---------------- scratch (device globals; no mallocs allowed) ----------------
__device__ float g_t   [MTOK*DIM];        // token-major residual stream
__device__ float g_tln [MTOK*DIM];
__device__ float g_xz  [MTOK*2*DI];       // in_proj output (xi | z), token-major
__device__ float g_xit [BATCH*DI*LL];     // xi transposed: (b,d,l) conv input
__device__ float g_xs2 [BATCH*2*DI*LL];   // conv out: [b][0]=row-major, [b][1]=col-major
__device__ float g_xdbl[BATCH*KDIR*38*LL];// x_proj out (b,k,c,l)  (k>=2 in flipped domain)
__device__ float g_dt  [BATCH*KDIR*DI*LL];// softplus(dt) (b,k,d,l)
__device__ float g_y   [BATCH*KDIR*DI*LL];// scan out incl. D*x (b,k,d,l)
__device__ float g_ysum[BATCH*DI*LL];     // combined directions (b,d,l)
__device__ float g_g   [MTOK*DI];         // gated+normed, token-major
__device__ float g_t2  [MTOK*DIM];
__device__ float g_hln [MTOK*DIM];
__device__ float g_a1  [MTOK*HID];
__device__ float g_tf  [MTOK*DIM];

// ---------------- tiled transposes ----------------
// x (b,96,L) -> t (b*L,96)
__global__ void transpose_in_kernel(const float* __restrict__ x, float* __restrict__ t) {
  __shared__ float s[32][33];
  int b = blockIdx.z, c0 = blockIdx.x * 32, l0 = blockIdx.y * 32;
  int tx = threadIdx.x, ty = threadIdx.y;
  #pragma unroll
  for (int i = 0; i < 4; i++) {
    int c = c0 + ty + i * 8;
    s[ty + i * 8][tx] = x[((size_t)b * DIM + c) * LL + l0 + tx];
  }
  __syncthreads();
  #pragma unroll
  for (int i = 0; i < 4; i++) {
    int l = l0 + ty + i * 8;
    t[((size_t)b * LL + l) * DIM + c0 + tx] = s[tx][ty + i * 8];
  }
}

// xz (m,384) first 192 cols -> xit (b,192,L)
__global__ void transpose_xz_kernel(const float* __restrict__ xz, float* __restrict__ xit) {
  __shared__ float s[32][33];
  int b = blockIdx.z, d0 = blockIdx.x * 32, l0 = blockIdx.y * 32;
  int tx = threadIdx.x, ty = threadIdx.y;
  #pragma unroll
  for (int i = 0; i < 4; i++) {
    int l = l0 + ty + i * 8;
    s[ty + i * 8][tx] = xz[((size_t)b * LL + l) * (2 * DI) + d0 + tx];
  }
  __syncthreads();
  #pragma unroll
  for (int i = 0; i < 4; i++) {
    int d = d0 + ty + i * 8;
    xit[((size_t)b * DI + d) * LL + l0 + tx] = s[tx][ty + i * 8];
  }
}

// tf (m,96) -> out (b,96,L)
__global__ void transpose_out_kernel(const float* __restrict__ tf, float* __restrict__ out) {
  __shared__ float s[32][33];
  int b = blockIdx.z, c0 = blockIdx.x * 32, l0 = blockIdx.y * 32;
  int tx = threadIdx.x, ty = threadIdx.y;
  #pragma unroll
  for (int i = 0; i < 4; i++) {
    int l = l0 + ty + i * 8;
    s[ty + i * 8][tx] = tf[((size_t)b * LL + l) * DIM + c0 + tx];
  }
  __syncthreads();
  #pragma unroll
  for (int i = 0; i < 4; i++) {
    int c = c0 + ty + i * 8;
    out[((size_t)b * DIM + c) * LL + l0 + tx] = s[tx][ty + i * 8];
  }
}

// ---------------- layernorm over 96 (warp per token) ----------------
__global__ void ln96_kernel(const float* __restrict__ in, const float* __restrict__ g,
                            const float* __restrict__ bb, float* __restrict__ out) {
  int token = blockIdx.x * 8 + (threadIdx.x >> 5);
  int lane = threadIdx.x & 31;
  const float* x = in + (size_t)token * DIM;
  float v0 = x[lane], v1 = x[lane + 32], v2 = x[lane + 64];
  float s = v0 + v1 + v2;
  float s2 = v0 * v0 + v1 * v1 + v2 * v2;
  #pragma unroll
  for (int o = 16; o; o >>= 1) {
    s  += __shfl_xor_sync(0xffffffffu, s, o);
    s2 += __shfl_xor_sync(0xffffffffu, s2, o);
  }
  const float inv = 1.f / 96.f;
  float mu = s * inv;
  float var = s2 * inv - mu * mu;
  float rs = rsqrtf(var + 1e-5f);
  float* o = out + (size_t)token * DIM;
  o[lane]      = (v0 - mu) * rs * g[lane]      + bb[lane];
  o[lane + 32] = (v1 - mu) * rs * g[lane + 32] + bb[lane + 32];
  o[lane + 64] = (v2 - mu) * rs * g[lane + 64] + bb[lane + 64];
}

// ---------------- generic fp32 GEMM: C = A(MxK) * B(NxK)^T + bias (+add, +gelu) ----------------
template <int ACT>  // 0 none, 1 gelu(exact)
__global__ void __launch_bounds__(256) gemm_kernel(
    const float* __restrict__ A, const float* __restrict__ B,
    const float* __restrict__ bias, const float* __restrict__ add,
    float* __restrict__ C, int M, int N, int K) {
  __shared__ __align__(16) float As[16][68];
  __shared__ __align__(16) float Bs[16][68];
  int nt = blockIdx.x * 64, mt = blockIdx.y * 64;
  int tid = threadIdx.x;
  int lr = tid >> 2, lk = (tid & 3) << 2;
  int tm = (tid >> 4) << 2, tn = (tid & 15) << 2;
  float acc[4][4] = {};
  for (int k0 = 0; k0 < K; k0 += 16) {
    float4 av = *(const float4*)(A + (size_t)(mt + lr) * K + k0 + lk);
    As[lk + 0][lr] = av.x; As[lk + 1][lr] = av.y; As[lk + 2][lr] = av.z; As[lk + 3][lr] = av.w;
    float4 bv = make_float4(0.f, 0.f, 0.f, 0.f);
    if (nt + lr < N) bv = *(const float4*)(B + (size_t)(nt + lr) * K + k0 + lk);
    Bs[lk + 0][lr] = bv.x; Bs[lk + 1][lr] = bv.y; Bs[lk + 2][lr] = bv.z; Bs[lk + 3][lr] = bv.w;
    __syncthreads();
    #pragma unroll
    for (int kk = 0; kk < 16; kk++) {
      float4 a4 = *(const float4*)&As[kk][tm];
      float4 b4 = *(const float4*)&Bs[kk][tn];
      float ar[4] = {a4.x, a4.y, a4.z, a4.w};
      float br[4] = {b4.x, b4.y, b4.z, b4.w};
      #pragma unroll
      for (int i = 0; i < 4; i++)
        #pragma unroll
        for (int j = 0; j < 4; j++) acc[i][j] = fmaf(ar[i], br[j], acc[i][j]);
    }
    __syncthreads();
  }
  #pragma unroll
  for (int i = 0; i < 4; i++) {
    int m = mt + tm + i;
    #pragma unroll
    for (int j = 0; j < 4; j++) {
      int n = nt + tn + j;
      if (n < N) {
        float v = acc[i][j] + bias[n];
        if (ACT == 1) v = 0.5f * v * (1.f + erff(v * 0.70710678118654752f));
        if (add) v += add[(size_t)m * N + n];
        C[(size_t)m * N + n] = v;
      }
    }
  }
}

// ---------------- depthwise 3x3 conv + bias + silu, dual-layout store ----------------
__global__ void __launch_bounds__(256) conv_kernel(const float* __restrict__ xi,
                                                   const float* __restrict__ cw,
                                                   const float* __restrict__ cb,
                                                   float* __restrict__ xs2) {
  int bd = blockIdx.x; int b = bd / DI, d = bd % DI;
  int h0 = blockIdx.y * 32, w0 = blockIdx.z * 32;
  __shared__ float tin[34][36];
  __shared__ float tout[32][33];
  int tid = threadIdx.x;
  const float* src = xi + (size_t)bd * LL;
  for (int i = tid; i < 34 * 34; i += 256) {
    int r = i / 34, c = i % 34;
    int gh = h0 + r - 1, gw = w0 + c - 1;
    float v = 0.f;
    if (gh >= 0 && gh < HH && gw >= 0 && gw < WW) v = src[gh * WW + gw];
    tin[r][c] = v;
  }
  float w[9];
  #pragma unroll
  for (int i = 0; i < 9; i++) w[i] = cw[d * 9 + i];
  float bias = cb[d];
  __syncthreads();
  float* orow = xs2 + (((size_t)b * 2 + 0) * DI + d) * LL;
  float* ocol = xs2 + (((size_t)b * 2 + 1) * DI + d) * LL;
  int c = tid & 31;
  #pragma unroll
  for (int i = 0; i < 4; i++) {
    int r = (tid >> 5) + i * 8;
    float acc = bias;
    #pragma unroll
    for (int ki = 0; ki < 3; ki++)
      #pragma unroll
      for (int kj = 0; kj < 3; kj++)
        acc = fmaf(w[ki * 3 + kj], tin[r + ki][c + kj], acc);
    float sv = acc / (1.f + __expf(-acc));  // silu
    orow[(h0 + r) * WW + w0 + c] = sv;
    tout[r][c] = sv;
  }
  __syncthreads();
  #pragma unroll
  for (int i = 0; i < 4; i++) {
    int cc = (tid >> 5) + i * 8;
    int rr = tid & 31;
    ocol[(w0 + cc) * HH + h0 + rr] = tout[rr][cc];
  }
}

// ---------------- x_proj: x_dbl[b,k,c,l] = sum_d W[k,c,d] * xs[b,k,d,l] ----------------
// k>=2 directions read the k-2 buffer back-to-front (flipped scan domain).
__global__ void __launch_bounds__(256) xproj_kernel(const float* __restrict__ xs2,
                                                    const float* __restrict__ xw,
                                                    float* __restrict__ xdbl) {
  int bk = blockIdx.x; int b = bk >> 2, k = bk & 3;
  int l0 = blockIdx.y * 128;
  bool rev = (k >= 2); int kb = k & 1;
  __shared__ float Xs[32][128];
  __shared__ float Ws[38][32];
  int tid = threadIdx.x;
  int li = tid & 127, cg = tid >> 7;  // cg in {0,1}
  float acc[19];
  #pragma unroll
  for (int i = 0; i < 19; i++) acc[i] = 0.f;
  const float* xbase = xs2 + ((size_t)(b * 2 + kb) * DI) * LL;
  for (int d0 = 0; d0 < DI; d0 += 32) {
    for (int i = tid; i < 32 * 128; i += 256) {
      int dd = i >> 7, ll = i & 127;
      int pos = rev ? (LL - 1 - (l0 + ll)) : (l0 + ll);
      Xs[dd][ll] = xbase[(size_t)(d0 + dd) * LL + pos];
    }
    for (int i = tid; i < 38 * 32; i += 256) {
      int cc = i >> 5, dd = i & 31;
      Ws[cc][dd] = xw[((size_t)k * 38 + cc) * DI + d0 + dd];
    }
    __syncthreads();
    #pragma unroll 8
    for (int dd = 0; dd < 32; dd++) {
      float xv = Xs[dd][li];
      #pragma unroll
      for (int i = 0; i < 19; i++) acc[i] = fmaf(Ws[cg + 2 * i][dd], xv, acc[i]);
    }
    __syncthreads();
  }
  #pragma unroll
  for (int i = 0; i < 19; i++) {
    int cc = cg + 2 * i;
    xdbl[((size_t)bk * 38 + cc) * LL + l0 + li] = acc[i];
  }
}

// ---------------- dt projection + softplus ----------------
__global__ void dt_kernel(const float* __restrict__ xdbl, const float* __restrict__ dtw,
                          const float* __restrict__ dtbv, float* __restrict__ dtout) {
  int id = blockIdx.x;            // bk*192 + d
  int bk = id / DI, d = id % DI;
  int k = bk & 3;
  float w[DTR];
  #pragma unroll
  for (int r = 0; r < DTR; r++) w[r] = dtw[((size_t)k * DI + d) * DTR + r];
  float bias = dtbv[k * DI + d];
  const float* xr = xdbl + (size_t)bk * 38 * LL;
  float* o = dtout + (size_t)id * LL;
  for (int l = threadIdx.x; l < LL; l += 256) {
    float s = bias;
    #pragma unroll
    for (int r = 0; r < DTR; r++) s = fmaf(w[r], xr[r * LL + l], s);
    // softplus = max(s,0) + log(1 + exp(-|s|))  (fast intrinsics, rel err ~2^-21)
    o[l] = fmaxf(s, 0.f) + __logf(1.f + __expf(-fabsf(s)));
  }
}

// ---------------- selective scan ----------------
// warp = 4 channels x 8 lanes; each lane holds states n8 and n8+8. D*x folded in.
__global__ void __launch_bounds__(128) scan_kernel(
    const float* __restrict__ dtb, const float* __restrict__ xs2,
    const float* __restrict__ xdbl, const float* __restrict__ A_logs,
    const float* __restrict__ Ds, float* __restrict__ y) {
  int bk = blockIdx.x;
  int b = bk >> 2, k = bk & 3;
  int lane = threadIdx.x & 31, warp = threadIdx.x >> 5;
  int group = lane >> 3, n8 = lane & 7;
  int d = blockIdx.y * 16 + warp * 4 + group;
  bool rev = (k >= 2);
  const float* dtp = dtb + ((size_t)bk * DI + d) * LL;
  const float* xp  = xs2 + (((size_t)b * 2 + (k & 1)) * DI + d) * LL;
  const float* Bp0 = xdbl + ((size_t)bk * 38 + 6 + n8) * LL;
  const float* Bp1 = Bp0 + 8 * LL;
  const float* Cp0 = xdbl + ((size_t)bk * 38 + 22 + n8) * LL;
  const float* Cp1 = Cp0 + 8 * LL;
  float* yo = y + ((size_t)bk * DI + d) * LL;
  int ad = (k * DI + d) * NST;
  float a0 = -__expf(A_logs[ad + n8]);
  float a1 = -__expf(A_logs[ad + n8 + 8]);
  float Dv = Ds[k * DI + d];
  float h0 = 0.f, h1 = 0.f;
  for (int l = 0; l < LL; l += 4) {
    float4 dtv = *(const float4*)(dtp + l);
    float4 xv;
    if (!rev) {
      xv = *(const float4*)(xp + l);
    } else {
      float4 t = *(const float4*)(xp + (LL - 4 - l));
      xv = make_float4(t.w, t.z, t.y, t.x);
    }
    float4 B0v = *(const float4*)(Bp0 + l);
    float4 B1v = *(const float4*)(Bp1 + l);
    float4 C0v = *(const float4*)(Cp0 + l);
    float4 C1v = *(const float4*)(Cp1 + l);
    float dts[4] = {dtv.x, dtv.y, dtv.z, dtv.w};
    float xss[4] = {xv.x, xv.y, xv.z, xv.w};
    float B0s[4] = {B0v.x, B0v.y, B0v.z, B0v.w};
    float B1s[4] = {B1v.x, B1v.y, B1v.z, B1v.w};
    float C0s[4] = {C0v.x, C0v.y, C0v.z, C0v.w};
    float C1s[4] = {C1v.x, C1v.y, C1v.z, C1v.w};
    float yp[4];
    #pragma unroll
    for (int j = 0; j < 4; j++) {
      float dt = dts[j];
      float dA0 = __expf(dt * a0);
      float dA1 = __expf(dt * a1);
      float dtx = dt * xss[j];
      h0 = fmaf(h0, dA0, dtx * B0s[j]);
      h1 = fmaf(h1, dA1, dtx * B1s[j]);
      yp[j] = fmaf(h1, C1s[j], h0 * C0s[j]);
    }
    #pragma unroll
    for (int j = 0; j < 4; j++) {
      yp[j] += __shfl_xor_sync(0xffffffffu, yp[j], 1);
      yp[j] += __shfl_xor_sync(0xffffffffu, yp[j], 2);
      yp[j] += __shfl_xor_sync(0xffffffffu, yp[j], 4);
    }
    if (n8 == 0) {
      float4 o = make_float4(fmaf(Dv, xss[0], yp[0]), fmaf(Dv, xss[1], yp[1]),
                             fmaf(Dv, xss[2], yp[2]), fmaf(Dv, xss[3], yp[3]));
      *(float4*)(yo + l) = o;
    }
  }
}

// ---------------- direction combine: ysum[b,d,h*64+w] ----------------
// = y0[p] + y1[w*64+h] + y2[L-1-p] + y3[L-1-(w*64+h)]   (y2/y3 stored in flipped domain)
__global__ void __launch_bounds__(256) combine_kernel(const float* __restrict__ y,
                                                      float* __restrict__ ysum) {
  int bd = blockIdx.x; int b = bd / DI, d = bd % DI;
  int h0 = blockIdx.y * 32, w0 = blockIdx.z * 32;
  const float* y0 = y + ((size_t)((b * 4 + 0) * DI + d)) * LL;
  const float* y1 = y + ((size_t)((b * 4 + 1) * DI + d)) * LL;
  const float* y2 = y + ((size_t)((b * 4 + 2) * DI + d)) * LL;
  const float* y3 = y + ((size_t)((b * 4 + 3) * DI + d)) * LL;
  __shared__ float sm1[32][33];
  __shared__ float sm3[32][33];
  int tid = threadIdx.x;
  int c = tid & 31;
  int r3b = 32 - w0, c3b = 32 - h0;   // base offsets for reversed y3 tile
  #pragma unroll
  for (int i = 0; i < 4; i++) {
    int r = (tid >> 5) + i * 8;
    sm1[r][c] = y1[(w0 + r) * 64 + h0 + c];
    sm3[r][c] = y3[(r3b + r) * 64 + c3b + c];
  }
  __syncthreads();
  float* od = ysum + ((size_t)b * DI + d) * LL;
  #pragma unroll
  for (int i = 0; i < 4; i++) {
    int ro = (tid >> 5) + i * 8;
    int p = (h0 + ro) * 64 + w0 + c;
    float v = y0[p] + sm1[c][ro] + y2[LL - 1 - p] + sm3[31 - c][31 - ro];
    od[p] = v;
  }
}

// ---------------- transpose + LN(192) + silu(z) gate -> g (token-major) ----------------
__global__ void __launch_bounds__(256) gatenorm_kernel(
    const float* __restrict__ ysum, const float* __restrict__ xz,
    const float* __restrict__ g, const float* __restrict__ bb,
    float* __restrict__ out) {
  __shared__ float s[DI][33];
  int b = blockIdx.y;
  int l0 = blockIdx.x * 32;
  int tid = threadIdx.x;
  for (int i = tid; i < DI * 32; i += 256) {
    int d = i >> 5, j = i & 31;
    s[d][j] = ysum[((size_t)b * DI + d) * LL + l0 + j];
  }
  __syncthreads();
  int warp = tid >> 5, lane = tid & 31;
  for (int t = 0; t < 4; t++) {
    int j = warp * 4 + t;
    float v[6], su = 0.f, sq = 0.f;
    #pragma unroll
    for (int m = 0; m < 6; m++) {
      v[m] = s[lane + 32 * m][j];
      su += v[m];
      sq += v[m] * v[m];
    }
    #pragma unroll
    for (int o = 16; o; o >>= 1) {
      su += __shfl_xor_sync(0xffffffffu, su, o);
      sq += __shfl_xor_sync(0xffffffffu, sq, o);
    }
    const float inv = 1.f / 192.f;
    float mu = su * inv;
    float var = sq * inv - mu * mu;
    float rs = rsqrtf(var + 1e-5f);
    size_t tok = (size_t)b * LL + l0 + j;
    #pragma unroll
    for (int m = 0; m < 6; m++) {
      int d = lane + 32 * m;
      float zn = xz[tok * (2 * DI) + DI + d];
      float sz = zn / (1.f + __expf(-zn));
      out[tok * DI + d] = ((v[m] - mu) * rs * g[d] + bb[d]) * sz;
    }
  }
}

// ---------------- host launcher ----------------
extern "C" void kernel_launch(void* const* d_in, const int* in_sizes, int n_in,
                              void* d_out, int out_size) {
  (void)in_sizes; (void)n_in;
  const float* x          = (const float*)d_in[0];
  const float* norm1_g    = (const float*)d_in[1];
  const float* norm1_b    = (const float*)d_in[2];
  const float* in_proj_w  = (const float*)d_in[3];
  const float* in_proj_b  = (const float*)d_in[4];
  const float* conv_w     = (const float*)d_in[5];
  const float* conv_b     = (const float*)d_in[6];
  const float* x_proj_w   = (const float*)d_in[7];
  const float* dt_projs_w = (const float*)d_in[8];
  const float* dt_projs_b = (const float*)d_in[9];
  const float* A_logs     = (const float*)d_in[10];
  const float* Ds         = (const float*)d_in[11];
  const float* out_norm_g = (const float*)d_in[12];
  const float* out_norm_b = (const float*)d_in[13];
  const float* out_proj_w = (const float*)d_in[14];
  const float* out_proj_b = (const float*)d_in[15];
  const float* norm2_g    = (const float*)d_in[16];
  const float* norm2_b    = (const float*)d_in[17];
  const float* mlp_w1     = (const float*)d_in[18];
  const float* mlp_b1     = (const float*)d_in[19];
  const float* mlp_w2     = (const float*)d_in[20];
  const float* mlp_b2     = (const float*)d_in[21];
  float* out = (float*)d_out;

  float *t, *tln, *xz, *xit, *xs2, *xdbl, *dtv, *yv, *ysum, *gg, *t2, *hln, *a1, *tf;
  cudaGetSymbolAddress((void**)&t,    g_t);
  cudaGetSymbolAddress((void**)&tln,  g_tln);
  cudaGetSymbolAddress((void**)&xz,   g_xz);
  cudaGetSymbolAddress((void**)&xit,  g_xit);
  cudaGetSymbolAddress((void**)&xs2,  g_xs2);
  cudaGetSymbolAddress((void**)&xdbl, g_xdbl);
  cudaGetSymbolAddress((void**)&dtv,  g_dt);
  cudaGetSymbolAddress((void**)&yv,   g_y);
  cudaGetSymbolAddress((void**)&ysum, g_ysum);
  cudaGetSymbolAddress((void**)&gg,   g_g);
  cudaGetSymbolAddress((void**)&t2,   g_t2);
  cudaGetSymbolAddress((void**)&hln,  g_hln);
  cudaGetSymbolAddress((void**)&a1,   g_a1);
  cudaGetSymbolAddress((void**)&tf,   g_tf);

  dim3 tb(32, 8);

  // 1. NCHW -> token-major
  transpose_in_kernel<<<dim3(3, 128, 4), tb>>>(x, t);
  // 2. LN1
  ln96_kernel<<<2048, 256>>>(t, norm1_g, norm1_b, tln);
  // 3. in_proj: (M,96)x(384,96)^T
  gemm_kernel<0><<<dim3(6, 256), 256>>>(tln, in_proj_w, in_proj_b, nullptr, xz, MTOK, 2 * DI, DIM);
  // 4. xi -> (b,192,L)
  transpose_xz_kernel<<<dim3(6, 128, 4), tb>>>(xz, xit);
  // 5. depthwise conv + silu, row-major + col-major copies
  conv_kernel<<<dim3(BATCH * DI, 2, 2), 256>>>(xit, conv_w, conv_b, xs2);
  // 6. x_proj for all 4 directions
  xproj_kernel<<<dim3(16, 32), 256>>>(xs2, x_proj_w, xdbl);
  // 7. dt projection + softplus
  dt_kernel<<<16 * DI, 256>>>(xdbl, dt_projs_w, dt_projs_b, dtv);
  // 8. selective scan (+ D*x)
  scan_kernel<<<dim3(16, 12), 128>>>(dtv, xs2, xdbl, A_logs, Ds, yv);
  // 9. combine 4 directions
  combine_kernel<<<dim3(BATCH * DI, 2, 2), 256>>>(yv, ysum);
  // 10. transpose + out_norm + silu(z) gate
  gatenorm_kernel<<<dim3(128, 4), 256>>>(ysum, xz, out_norm_g, out_norm_b, gg);
  // 11. out_proj + residual: t2 = t + ss
  gemm_kernel<0><<<dim3(2, 256), 256>>>(gg, out_proj_w, out_proj_b, t, t2, MTOK, DIM, DI);
  // 12. LN2
  ln96_kernel<<<2048, 256>>>(t2, norm2_g, norm2_b, hln);
  // 13. mlp1 + exact gelu
  gemm_kernel<1><<<dim3(6, 256), 256>>>(hln, mlp_w1, mlp_b1, nullptr, a1, MTOK, HID, DIM);
  // 14. mlp2 + residual
  gemm_kernel<0><<<dim3(2, 256), 256>>>(a1, mlp_w2, mlp_b2, t2, tf, MTOK, DIM, HID);
  // 15. token-major -> NCHW
  transpose_out_kernel<<<dim3(3, 128, 4), tb>>>(tf, out);
}

// round 14
// speedup vs baseline: 1.4801x; 1.4801x over previous
#include <cuda_runtime.h>
#include <cuda_bf16.h>
#include <math.h>

// ---------------- problem constants ----------------
#define BATCH 4
#define DIM 96
#define DI 192           // D_INNER
#define NST 16           // D_STATE
#define DTR 6            // DT_RANK
#define KDIR 4
#define HID 384
#define HH 64
#define WW 64
#define LL 4096          // H*W
#define MTOK (BATCH*LL)  // 16384

// ---------------- scratch (device globals; no mallocs allowed) ----------------
__device__ float g_t   [MTOK*DIM];        // token-major residual stream
__device__ float g_tln [MTOK*DIM];
__device__ float g_xz  [MTOK*2*DI];       // in_proj output (xi | z), token-major
__device__ float g_xit [BATCH*DI*LL];     // xi transposed: (b,d,l) conv input
__device__ float g_xs2 [BATCH*2*DI*LL];   // conv out: [b][0]=row-major, [b][1]=col-major
__device__ float g_xdbl[BATCH*KDIR*38*LL];// x_proj out (b,k,c,l)  (k>=2 in flipped domain)
__device__ float g_dt  [BATCH*KDIR*DI*LL];// softplus(dt) (b,k,d,l)
__device__ float g_y   [BATCH*KDIR*DI*LL];// scan out incl. D*x (b,k,d,l)
__device__ float g_ysum[BATCH*DI*LL];     // combined directions (b,d,l)
__device__ float g_g   [MTOK*DI];         // gated+normed, token-major
__device__ float g_t2  [MTOK*DIM];
__device__ float g_hln [MTOK*DIM];
__device__ float g_a1  [MTOK*HID];
__device__ float g_tf  [MTOK*DIM];

// ---------------- tiled transposes ----------------
// x (b,96,L) -> t (b*L,96)
__global__ void transpose_in_kernel(const float* __restrict__ x, float* __restrict__ t) {
  __shared__ float s[32][33];
  int b = blockIdx.z, c0 = blockIdx.x * 32, l0 = blockIdx.y * 32;
  int tx = threadIdx.x, ty = threadIdx.y;
  #pragma unroll
  for (int i = 0; i < 4; i++) {
    int c = c0 + ty + i * 8;
    s[ty + i * 8][tx] = x[((size_t)b * DIM + c) * LL + l0 + tx];
  }
  __syncthreads();
  #pragma unroll
  for (int i = 0; i < 4; i++) {
    int l = l0 + ty + i * 8;
    t[((size_t)b * LL + l) * DIM + c0 + tx] = s[tx][ty + i * 8];
  }
}

// xz (m,384) first 192 cols -> xit (b,192,L)
__global__ void transpose_xz_kernel(const float* __restrict__ xz, float* __restrict__ xit) {
  __shared__ float s[32][33];
  int b = blockIdx.z, d0 = blockIdx.x * 32, l0 = blockIdx.y * 32;
  int tx = threadIdx.x, ty = threadIdx.y;
  #pragma unroll
  for (int i = 0; i < 4; i++) {
    int l = l0 + ty + i * 8;
    s[ty + i * 8][tx] = xz[((size_t)b * LL + l) * (2 * DI) + d0 + tx];
  }
  __syncthreads();
  #pragma unroll
  for (int i = 0; i < 4; i++) {
    int d = d0 + ty + i * 8;
    xit[((size_t)b * DI + d) * LL + l0 + tx] = s[tx][ty + i * 8];
  }
}

// tf (m,96) -> out (b,96,L)
__global__ void transpose_out_kernel(const float* __restrict__ tf, float* __restrict__ out) {
  __shared__ float s[32][33];
  int b = blockIdx.z, c0 = blockIdx.x * 32, l0 = blockIdx.y * 32;
  int tx = threadIdx.x, ty = threadIdx.y;
  #pragma unroll
  for (int i = 0; i < 4; i++) {
    int l = l0 + ty + i * 8;
    s[ty + i * 8][tx] = tf[((size_t)b * LL + l) * DIM + c0 + tx];
  }
  __syncthreads();
  #pragma unroll
  for (int i = 0; i < 4; i++) {
    int c = c0 + ty + i * 8;
    out[((size_t)b * DIM + c) * LL + l0 + tx] = s[tx][ty + i * 8];
  }
}

// ---------------- layernorm over 96 (warp per token) ----------------
__global__ void ln96_kernel(const float* __restrict__ in, const float* __restrict__ g,
                            const float* __restrict__ bb, float* __restrict__ out) {
  int token = blockIdx.x * 8 + (threadIdx.x >> 5);
  int lane = threadIdx.x & 31;
  const float* x = in + (size_t)token * DIM;
  float v0 = x[lane], v1 = x[lane + 32], v2 = x[lane + 64];
  float s = v0 + v1 + v2;
  float s2 = v0 * v0 + v1 * v1 + v2 * v2;
  #pragma unroll
  for (int o = 16; o; o >>= 1) {
    s  += __shfl_xor_sync(0xffffffffu, s, o);
    s2 += __shfl_xor_sync(0xffffffffu, s2, o);
  }
  const float inv = 1.f / 96.f;
  float mu = s * inv;
  float var = s2 * inv - mu * mu;
  float rs = rsqrtf(var + 1e-5f);
  float* o = out + (size_t)token * DIM;
  o[lane]      = (v0 - mu) * rs * g[lane]      + bb[lane];
  o[lane + 32] = (v1 - mu) * rs * g[lane + 32] + bb[lane + 32];
  o[lane + 64] = (v2 - mu) * rs * g[lane + 64] + bb[lane + 64];
}

// ---------------- generic fp32 GEMM: C = A(MxK) * B(NxK)^T + bias (+add, +gelu) ----------------
template <int ACT>  // 0 none, 1 gelu(exact)
__global__ void __launch_bounds__(256) gemm_kernel(
    const float* __restrict__ A, const float* __restrict__ B,
    const float* __restrict__ bias, const float* __restrict__ add,
    float* __restrict__ C, int M, int N, int K) {
  __shared__ __align__(16) float As[16][68];
  __shared__ __align__(16) float Bs[16][68];
  int nt = blockIdx.x * 64, mt = blockIdx.y * 64;
  int tid = threadIdx.x;
  int lr = tid >> 2, lk = (tid & 3) << 2;
  int tm = (tid >> 4) << 2, tn = (tid & 15) << 2;
  float acc[4][4] = {};
  for (int k0 = 0; k0 < K; k0 += 16) {
    float4 av = *(const float4*)(A + (size_t)(mt + lr) * K + k0 + lk);
    As[lk + 0][lr] = av.x; As[lk + 1][lr] = av.y; As[lk + 2][lr] = av.z; As[lk + 3][lr] = av.w;
    float4 bv = make_float4(0.f, 0.f, 0.f, 0.f);
    if (nt + lr < N) bv = *(const float4*)(B + (size_t)(nt + lr) * K + k0 + lk);
    Bs[lk + 0][lr] = bv.x; Bs[lk + 1][lr] = bv.y; Bs[lk + 2][lr] = bv.z; Bs[lk + 3][lr] = bv.w;
    __syncthreads();
    #pragma unroll
    for (int kk = 0; kk < 16; kk++) {
      float4 a4 = *(const float4*)&As[kk][tm];
      float4 b4 = *(const float4*)&Bs[kk][tn];
      float ar[4] = {a4.x, a4.y, a4.z, a4.w};
      float br[4] = {b4.x, b4.y, b4.z, b4.w};
      #pragma unroll
      for (int i = 0; i < 4; i++)
        #pragma unroll
        for (int j = 0; j < 4; j++) acc[i][j] = fmaf(ar[i], br[j], acc[i][j]);
    }
    __syncthreads();
  }
  #pragma unroll
  for (int i = 0; i < 4; i++) {
    int m = mt + tm + i;
    #pragma unroll
    for (int j = 0; j < 4; j++) {
      int n = nt + tn + j;
      if (n < N) {
        float v = acc[i][j] + bias[n];
        if (ACT == 1) v = 0.5f * v * (1.f + erff(v * 0.70710678118654752f));
        if (add) v += add[(size_t)m * N + n];
        C[(size_t)m * N + n] = v;
      }
    }
  }
}

// ---------------- depthwise 3x3 conv + bias + silu, dual-layout store ----------------
__global__ void __launch_bounds__(256) conv_kernel(const float* __restrict__ xi,
                                                   const float* __restrict__ cw,
                                                   const float* __restrict__ cb,
                                                   float* __restrict__ xs2) {
  int bd = blockIdx.x; int b = bd / DI, d = bd % DI;
  int h0 = blockIdx.y * 32, w0 = blockIdx.z * 32;
  __shared__ float tin[34][36];
  __shared__ float tout[32][33];
  int tid = threadIdx.x;
  const float* src = xi + (size_t)bd * LL;
  for (int i = tid; i < 34 * 34; i += 256) {
    int r = i / 34, c = i % 34;
    int gh = h0 + r - 1, gw = w0 + c - 1;
    float v = 0.f;
    if (gh >= 0 && gh < HH && gw >= 0 && gw < WW) v = src[gh * WW + gw];
    tin[r][c] = v;
  }
  float w[9];
  #pragma unroll
  for (int i = 0; i < 9; i++) w[i] = cw[d * 9 + i];
  float bias = cb[d];
  __syncthreads();
  float* orow = xs2 + (((size_t)b * 2 + 0) * DI + d) * LL;
  float* ocol = xs2 + (((size_t)b * 2 + 1) * DI + d) * LL;
  int c = tid & 31;
  #pragma unroll
  for (int i = 0; i < 4; i++) {
    int r = (tid >> 5) + i * 8;
    float acc = bias;
    #pragma unroll
    for (int ki = 0; ki < 3; ki++)
      #pragma unroll
      for (int kj = 0; kj < 3; kj++)
        acc = fmaf(w[ki * 3 + kj], tin[r + ki][c + kj], acc);
    float sv = acc / (1.f + __expf(-acc));  // silu
    orow[(h0 + r) * WW + w0 + c] = sv;
    tout[r][c] = sv;
  }
  __syncthreads();
  #pragma unroll
  for (int i = 0; i < 4; i++) {
    int cc = (tid >> 5) + i * 8;
    int rr = tid & 31;
    ocol[(w0 + cc) * HH + h0 + rr] = tout[rr][cc];
  }
}

// ---------------- x_proj: x_dbl[b,k,c,l] = sum_d W[k,c,d] * xs[b,k,d,l] ----------------
// k>=2 directions read the k-2 buffer back-to-front (flipped scan domain).
// 2 l-columns per thread: 21 LDS per 38 FMA.
__global__ void __launch_bounds__(256) xproj_kernel(const float* __restrict__ xs2,
                                                    const float* __restrict__ xw,
                                                    float* __restrict__ xdbl) {
  int bk = blockIdx.x; int b = bk >> 2, k = bk & 3;
  int l0 = blockIdx.y * 256;
  bool rev = (k >= 2); int kb = k & 1;
  __shared__ float Xs[32][256];
  __shared__ float Ws[38][32];
  int tid = threadIdx.x;
  int li = tid & 127, cg = tid >> 7;  // cg in {0,1}
  float acc0[19], acc1[19];
  #pragma unroll
  for (int i = 0; i < 19; i++) { acc0[i] = 0.f; acc1[i] = 0.f; }
  const float* xbase = xs2 + ((size_t)(b * 2 + kb) * DI) * LL;
  for (int d0 = 0; d0 < DI; d0 += 32) {
    // load 32 x 256 X tile (as float4), reversing for k>=2
    for (int i = tid; i < 32 * 64; i += 256) {
      int dd = i >> 6, c4 = i & 63;
      if (!rev) {
        float4 v = *(const float4*)(xbase + (size_t)(d0 + dd) * LL + l0 + c4 * 4);
        *(float4*)&Xs[dd][c4 * 4] = v;
      } else {
        float4 t = *(const float4*)(xbase + (size_t)(d0 + dd) * LL + (LL - 4 - (l0 + c4 * 4)));
        Xs[dd][c4 * 4 + 0] = t.w; Xs[dd][c4 * 4 + 1] = t.z;
        Xs[dd][c4 * 4 + 2] = t.y; Xs[dd][c4 * 4 + 3] = t.x;
      }
    }
    for (int i = tid; i < 38 * 32; i += 256) {
      int cc = i >> 5, dd = i & 31;
      Ws[cc][dd] = xw[((size_t)k * 38 + cc) * DI + d0 + dd];
    }
    __syncthreads();
    #pragma unroll 4
    for (int dd = 0; dd < 32; dd++) {
      float xv0 = Xs[dd][li];
      float xv1 = Xs[dd][li + 128];
      #pragma unroll
      for (int i = 0; i < 19; i++) {
        float w = Ws[cg + 2 * i][dd];
        acc0[i] = fmaf(w, xv0, acc0[i]);
        acc1[i] = fmaf(w, xv1, acc1[i]);
      }
    }
    __syncthreads();
  }
  #pragma unroll
  for (int i = 0; i < 19; i++) {
    int cc = cg + 2 * i;
    xdbl[((size_t)bk * 38 + cc) * LL + l0 + li]       = acc0[i];
    xdbl[((size_t)bk * 38 + cc) * LL + l0 + 128 + li] = acc1[i];
  }
}

// ---------------- dt projection + softplus ----------------
__global__ void dt_kernel(const float* __restrict__ xdbl, const float* __restrict__ dtw,
                          const float* __restrict__ dtbv, float* __restrict__ dtout) {
  int id = blockIdx.x;            // bk*192 + d
  int bk = id / DI, d = id % DI;
  int k = bk & 3;
  float w[DTR];
  #pragma unroll
  for (int r = 0; r < DTR; r++) w[r] = dtw[((size_t)k * DI + d) * DTR + r];
  float bias = dtbv[k * DI + d];
  const float* xr = xdbl + (size_t)bk * 38 * LL;
  float* o = dtout + (size_t)id * LL;
  for (int l = threadIdx.x; l < LL; l += 256) {
    float s = bias;
    #pragma unroll
    for (int r = 0; r < DTR; r++) s = fmaf(w[r], xr[r * LL + l], s);
    // softplus = max(s,0) + log(1 + exp(-|s|))
    o[l] = fmaxf(s, 0.f) + __logf(1.f + __expf(-fabsf(s)));
  }
}

// ---------------- selective scan ----------------
// 64-thread blocks (2 warps); warp = 4 channels x 8 lanes; each lane holds
// states n8 and n8+8. B/C rows (shared across all d of a bk) staged through
// double-buffered smem in 64-step chunks, loaded coalesced and prefetched in
// registers; dt/x prefetched one iteration ahead. D*x folded in.
__global__ void __launch_bounds__(64) scan_kernel(
    const float* __restrict__ dtb, const float* __restrict__ xs2,
    const float* __restrict__ xdbl, const float* __restrict__ A_logs,
    const float* __restrict__ Ds, float* __restrict__ y) {
  int bk = blockIdx.x;
  int b = bk >> 2, k = bk & 3;
  int tid = threadIdx.x;
  int lane = tid & 31, warp = tid >> 5;
  int group = lane >> 3, n8 = lane & 7;
  int d = blockIdx.y * 8 + warp * 4 + group;
  bool rev = (k >= 2);
  const float* dtp = dtb + ((size_t)bk * DI + d) * LL;
  const float* xp  = xs2 + (((size_t)b * 2 + (k & 1)) * DI + d) * LL;
  const float* bcbase = xdbl + ((size_t)bk * 38 + 6) * LL;  // rows 6..37 = B(16) then C(16)
  float* yo = y + ((size_t)bk * DI + d) * LL;
  int ad = (k * DI + d) * NST;
  float a0 = -__expf(A_logs[ad + n8]);
  float a1 = -__expf(A_logs[ad + n8 + 8]);
  float Dv = Ds[k * DI + d];

  __shared__ float sB[2][32][68];  // row pad 68 -> banks 4*n8+j, conflict-free
  float4 creg[8];

  // prime chunk 0: 32 rows x 64 floats, coalesced (16 threads per row)
  #pragma unroll
  for (int q = 0; q < 8; q++) {
    int idx = q * 64 + tid; int row = idx >> 4; int c4 = idx & 15;
    creg[q] = *(const float4*)(bcbase + (size_t)row * LL + c4 * 4);
  }
  #pragma unroll
  for (int q = 0; q < 8; q++) {
    int idx = q * 64 + tid; int row = idx >> 4; int c4 = idx & 15;
    *(float4*)&sB[0][row][c4 * 4] = creg[q];
  }
  __syncthreads();

  float h0 = 0.f, h1 = 0.f;
  // prefetch dt/x for l=0
  float4 dtn = *(const float4*)(dtp);
  float4 xn;
  if (!rev) xn = *(const float4*)(xp);
  else { float4 t = *(const float4*)(xp + LL - 4); xn = make_float4(t.w, t.z, t.y, t.x); }

  int buf = 0;
  for (int ch = 0; ch < 64; ch++) {
    bool more = (ch + 1 < 64);
    if (more) {
      #pragma unroll
      for (int q = 0; q < 8; q++) {
        int idx = q * 64 + tid; int row = idx >> 4; int c4 = idx & 15;
        creg[q] = *(const float4*)(bcbase + (size_t)row * LL + (ch + 1) * 64 + c4 * 4);
      }
    }
    #pragma unroll 4
    for (int it = 0; it < 16; it++) {
      int l = ch * 64 + it * 4;
      float4 dtv = dtn, xv = xn;
      int ln = l + 4;
      if (ln < LL) {
        dtn = *(const float4*)(dtp + ln);
        if (!rev) xn = *(const float4*)(xp + ln);
        else { float4 t = *(const float4*)(xp + LL - 4 - ln); xn = make_float4(t.w, t.z, t.y, t.x); }
      }
      int lc = it * 4;
      float4 B0v = *(const float4*)&sB[buf][n8     ][lc];
      float4 B1v = *(const float4*)&sB[buf][n8 + 8 ][lc];
      float4 C0v = *(const float4*)&sB[buf][n8 + 16][lc];
      float4 C1v = *(const float4*)&sB[buf][n8 + 24][lc];
      float dts[4] = {dtv.x, dtv.y, dtv.z, dtv.w};
      float xss[4] = {xv.x, xv.y, xv.z, xv.w};
      float B0s[4] = {B0v.x, B0v.y, B0v.z, B0v.w};
      float B1s[4] = {B1v.x, B1v.y, B1v.z, B1v.w};
      float C0s[4] = {C0v.x, C0v.y, C0v.z, C0v.w};
      float C1s[4] = {C1v.x, C1v.y, C1v.z, C1v.w};
      float yp[4];
      #pragma unroll
      for (int j = 0; j < 4; j++) {
        float dt = dts[j];
        float dA0 = __expf(dt * a0);
        float dA1 = __expf(dt * a1);
        float dtx = dt * xss[j];
        h0 = fmaf(h0, dA0, dtx * B0s[j]);
        h1 = fmaf(h1, dA1, dtx * B1s[j]);
        yp[j] = fmaf(h1, C1s[j], h0 * C0s[j]);
      }
      #pragma unroll
      for (int j = 0; j < 4; j++) {
        yp[j] += __shfl_xor_sync(0xffffffffu, yp[j], 1);
        yp[j] += __shfl_xor_sync(0xffffffffu, yp[j], 2);
        yp[j] += __shfl_xor_sync(0xffffffffu, yp[j], 4);
      }
      if (n8 == 0) {
        float4 o = make_float4(fmaf(Dv, xss[0], yp[0]), fmaf(Dv, xss[1], yp[1]),
                               fmaf(Dv, xss[2], yp[2]), fmaf(Dv, xss[3], yp[3]));
        *(float4*)(yo + l) = o;
      }
    }
    if (more) {
      #pragma unroll
      for (int q = 0; q < 8; q++) {
        int idx = q * 64 + tid; int row = idx >> 4; int c4 = idx & 15;
        *(float4*)&sB[buf ^ 1][row][c4 * 4] = creg[q];
      }
    }
    __syncthreads();
    buf ^= 1;
  }
}

// ---------------- direction combine: ysum[b,d,h*64+w] ----------------
// = y0[p] + y1[w*64+h] + y2[L-1-p] + y3[L-1-(w*64+h)]   (y2/y3 stored in flipped domain)
__global__ void __launch_bounds__(256) combine_kernel(const float* __restrict__ y,
                                                      float* __restrict__ ysum) {
  int bd = blockIdx.x; int b = bd / DI, d = bd % DI;
  int h0 = blockIdx.y * 32, w0 = blockIdx.z * 32;
  const float* y0 = y + ((size_t)((b * 4 + 0) * DI + d)) * LL;
  const float* y1 = y + ((size_t)((b * 4 + 1) * DI + d)) * LL;
  const float* y2 = y + ((size_t)((b * 4 + 2) * DI + d)) * LL;
  const float* y3 = y + ((size_t)((b * 4 + 3) * DI + d)) * LL;
  __shared__ float sm1[32][33];
  __shared__ float sm3[32][33];
  int tid = threadIdx.x;
  int c = tid & 31;
  int r3b = 32 - w0, c3b = 32 - h0;   // base offsets for reversed y3 tile
  #pragma unroll
  for (int i = 0; i < 4; i++) {
    int r = (tid >> 5) + i * 8;
    sm1[r][c] = y1[(w0 + r) * 64 + h0 + c];
    sm3[r][c] = y3[(r3b + r) * 64 + c3b + c];
  }
  __syncthreads();
  float* od = ysum + ((size_t)b * DI + d) * LL;
  #pragma unroll
  for (int i = 0; i < 4; i++) {
    int ro = (tid >> 5) + i * 8;
    int p = (h0 + ro) * 64 + w0 + c;
    float v = y0[p] + sm1[c][ro] + y2[LL - 1 - p] + sm3[31 - c][31 - ro];
    od[p] = v;
  }
}

// ---------------- transpose + LN(192) + silu(z) gate -> g (token-major) ----------------
__global__ void __launch_bounds__(256) gatenorm_kernel(
    const float* __restrict__ ysum, const float* __restrict__ xz,
    const float* __restrict__ g, const float* __restrict__ bb,
    float* __restrict__ out) {
  __shared__ float s[DI][33];
  int b = blockIdx.y;
  int l0 = blockIdx.x * 32;
  int tid = threadIdx.x;
  for (int i = tid; i < DI * 32; i += 256) {
    int d = i >> 5, j = i & 31;
    s[d][j] = ysum[((size_t)b * DI + d) * LL + l0 + j];
  }
  __syncthreads();
  int warp = tid >> 5, lane = tid & 31;
  for (int t = 0; t < 4; t++) {
    int j = warp * 4 + t;
    float v[6], su = 0.f, sq = 0.f;
    #pragma unroll
    for (int m = 0; m < 6; m++) {
      v[m] = s[lane + 32 * m][j];
      su += v[m];
      sq += v[m] * v[m];
    }
    #pragma unroll
    for (int o = 16; o; o >>= 1) {
      su += __shfl_xor_sync(0xffffffffu, su, o);
      sq += __shfl_xor_sync(0xffffffffu, sq, o);
    }
    const float inv = 1.f / 192.f;
    float mu = su * inv;
    float var = sq * inv - mu * mu;
    float rs = rsqrtf(var + 1e-5f);
    size_t tok = (size_t)b * LL + l0 + j;
    #pragma unroll
    for (int m = 0; m < 6; m++) {
      int d = lane + 32 * m;
      float zn = xz[tok * (2 * DI) + DI + d];
      float sz = zn / (1.f + __expf(-zn));
      out[tok * DI + d] = ((v[m] - mu) * rs * g[d] + bb[d]) * sz;
    }
  }
}

// ---------------- host launcher ----------------
extern "C" void kernel_launch(void* const* d_in, const int* in_sizes, int n_in,
                              void* d_out, int out_size) {
  (void)in_sizes; (void)n_in; (void)out_size;
  const float* x          = (const float*)d_in[0];
  const float* norm1_g    = (const float*)d_in[1];
  const float* norm1_b    = (const float*)d_in[2];
  const float* in_proj_w  = (const float*)d_in[3];
  const float* in_proj_b  = (const float*)d_in[4];
  const float* conv_w     = (const float*)d_in[5];
  const float* conv_b     = (const float*)d_in[6];
  const float* x_proj_w   = (const float*)d_in[7];
  const float* dt_projs_w = (const float*)d_in[8];
  const float* dt_projs_b = (const float*)d_in[9];
  const float* A_logs     = (const float*)d_in[10];
  const float* Ds         = (const float*)d_in[11];
  const float* out_norm_g = (const float*)d_in[12];
  const float* out_norm_b = (const float*)d_in[13];
  const float* out_proj_w = (const float*)d_in[14];
  const float* out_proj_b = (const float*)d_in[15];
  const float* norm2_g    = (const float*)d_in[16];
  const float* norm2_b    = (const float*)d_in[17];
  const float* mlp_w1     = (const float*)d_in[18];
  const float* mlp_b1     = (const float*)d_in[19];
  const float* mlp_w2     = (const float*)d_in[20];
  const float* mlp_b2     = (const float*)d_in[21];
  float* out = (float*)d_out;

  float *t, *tln, *xz, *xit, *xs2, *xdbl, *dtv, *yv, *ysum, *gg, *t2, *hln, *a1, *tf;
  cudaGetSymbolAddress((void**)&t,    g_t);
  cudaGetSymbolAddress((void**)&tln,  g_tln);
  cudaGetSymbolAddress((void**)&xz,   g_xz);
  cudaGetSymbolAddress((void**)&xit,  g_xit);
  cudaGetSymbolAddress((void**)&xs2,  g_xs2);
  cudaGetSymbolAddress((void**)&xdbl, g_xdbl);
  cudaGetSymbolAddress((void**)&dtv,  g_dt);
  cudaGetSymbolAddress((void**)&yv,   g_y);
  cudaGetSymbolAddress((void**)&ysum, g_ysum);
  cudaGetSymbolAddress((void**)&gg,   g_g);
  cudaGetSymbolAddress((void**)&t2,   g_t2);
  cudaGetSymbolAddress((void**)&hln,  g_hln);
  cudaGetSymbolAddress((void**)&a1,   g_a1);
  cudaGetSymbolAddress((void**)&tf,   g_tf);

  dim3 tb(32, 8);

  // 1. NCHW -> token-major
  transpose_in_kernel<<<dim3(3, 128, 4), tb>>>(x, t);
  // 2. LN1
  ln96_kernel<<<2048, 256>>>(t, norm1_g, norm1_b, tln);
  // 3. in_proj: (M,96)x(384,96)^T
  gemm_kernel<0><<<dim3(6, 256), 256>>>(tln, in_proj_w, in_proj_b, nullptr, xz, MTOK, 2 * DI, DIM);
  // 4. xi -> (b,192,L)
  transpose_xz_kernel<<<dim3(6, 128, 4), tb>>>(xz, xit);
  // 5. depthwise conv + silu, row-major + col-major copies
  conv_kernel<<<dim3(BATCH * DI, 2, 2), 256>>>(xit, conv_w, conv_b, xs2);
  // 6. x_proj for all 4 directions (256 l per block)
  xproj_kernel<<<dim3(16, 16), 256>>>(xs2, x_proj_w, xdbl);
  // 7. dt projection + softplus
  dt_kernel<<<16 * DI, 256>>>(xdbl, dt_projs_w, dt_projs_b, dtv);
  // 8. selective scan (+ D*x): 64-thread blocks, 8 channels each
  scan_kernel<<<dim3(16, 24), 64>>>(dtv, xs2, xdbl, A_logs, Ds, yv);
  // 9. combine 4 directions
  combine_kernel<<<dim3(BATCH * DI, 2, 2), 256>>>(yv, ysum);
  // 10. transpose + out_norm + silu(z) gate
  gatenorm_kernel<<<dim3(128, 4), 256>>>(ysum, xz, out_norm_g, out_norm_b, gg);
  // 11. out_proj + residual: t2 = t + ss
  gemm_kernel<0><<<dim3(2, 256), 256>>>(gg, out_proj_w, out_proj_b, t, t2, MTOK, DIM, DI);
  // 12. LN2
  ln96_kernel<<<2048, 256>>>(t2, norm2_g, norm2_b, hln);
  // 13. mlp1 + exact gelu
  gemm_kernel<1><<<dim3(6, 256), 256>>>(hln, mlp_w1, mlp_b1, nullptr, a1, MTOK, HID, DIM);
  // 14. mlp2 + residual
  gemm_kernel<0><<<dim3(2, 256), 256>>>(a1, mlp_w2, mlp_b2, t2, tf, MTOK, DIM, HID);
  // 15. token-major -> NCHW
  transpose_out_kernel<<<dim3(3, 128, 4), tb>>>(tf, out);
}